// round 6
// baseline (speedup 1.0000x reference)
#include <cuda_runtime.h>
#include <cuda_fp16.h>
#include <cstdint>

#define D_ 64
#define B_ 64
#define S_ 1024
#define L_ 512
#define O_ 10
#define NPAIR 256                       // site pairs per side
#define PAIRBLK_U64 4096                // 256 threads * 16 u64 = 32KB / pair

typedef unsigned long long u64;

__device__ float g_vL[B_][D_];
__device__ float g_wR[B_][D_];
__device__ __align__(16) u64 g_E[2 * NPAIR * PAIRBLK_U64];   // 16.78 MB fp16 E

// ---------- prep: E = W - I (fp16), thread-major chunked, sites pair-interleaved ----------
// grid 512: side = bx>>8, P = bx&255. Right side is transposed (l<->r) and
// site-reversed so the chain kernel is side-uniform.
// Unit (w,c,lane) at 16B index (w*8+c)*32+lane holds u64{l=q*16+2c}, u64{l=q*16+2c+1},
// each u64 = (half2 E[scan-even site], half2 E[scan-odd site]), q=lane&3, r=w*8+(lane>>2).
__global__ void prep_kernel(const float* __restrict__ Wl, const float* __restrict__ Wr) {
    extern __shared__ float tl[];       // 2 x 16384 floats (131072 B)
    int bx = blockIdx.x;
    int side = bx >> 8;
    int P = bx & 255;
    int tid = threadIdx.x;
    int s0 = side ? (511 - 2 * P) : (2 * P);
    int s1 = side ? (510 - 2 * P) : (2 * P + 1);
    const float* W = side ? Wr : Wl;
    const float4* src0 = (const float4*)(W + (size_t)s0 * 8192);
    const float4* src1 = (const float4*)(W + (size_t)s1 * 8192);
    float4* t0 = (float4*)tl;
    float4* t1 = (float4*)(tl + 16384);
    for (int i = tid; i < 2048; i += 256) { t0[i] = src0[i]; t1[i] = src1[i]; }
    __syncthreads();

    int lane = tid & 31, w = tid >> 5;
    int q = lane & 3, rloc = lane >> 2;
    int r = w * 8 + rloc;
    ulonglong2* dst = (ulonglong2*)(g_E + (size_t)bx * PAIRBLK_U64);
    #pragma unroll
    for (int c = 0; c < 8; c++) {
        u64 out[2];
        #pragma unroll
        for (int k = 0; k < 2; k++) {
            int l = q * 16 + 2 * c + k;
            int i0 = side ? (r * 128 + l * 2) : (l * 128 + r * 2);
            float d = (l == r) ? 1.0f : 0.0f;
            __half2 h0 = __floats2half2_rn(tl[i0] - d, tl[i0 + 1] - d);
            __half2 h1 = __floats2half2_rn(tl[16384 + i0] - d, tl[16384 + i0 + 1] - d);
            out[k] = ((u64)(*(uint32_t*)&h1) << 32) | (u64)(*(uint32_t*)&h0);
        }
        ulonglong2 v; v.x = out[0]; v.y = out[1];
        dst[(w * 8 + c) * 32 + lane] = v;
    }
}

// ---------- chain kernel ----------
// grid 64: side = bx>>5, batch pair bp = bx&31 -> batches 2bp, 2bp+1. 256 threads.
// Thread (r = w*8+(lane>>2), q = lane&3) handles l in [16q,16q+16) for both batches.
// v'[r] = v[r]*(x0+x1) + sum_l u0[l]*E0[l,r] + u1[l]*E1[l,r],  u_i = v[l]*x_i.
__global__ void __launch_bounds__(256, 1)
chain_kernel(const float* __restrict__ x) {
    __shared__ float2 xsh[2][L_];
    __shared__ __align__(16) u64 usm[2][D_][2];    // [site parity][l][local batch]

    int tid = threadIdx.x;
    int lane = tid & 31, w = tid >> 5;
    int q = lane & 3;
    int r = w * 8 + (lane >> 2);
    int side = blockIdx.x >> 5;
    int b0 = (blockIdx.x & 31) * 2;

    for (int nb = 0; nb < 2; nb++) {
        const float2* xs = (const float2*)x + (size_t)(b0 + nb) * S_ + side * L_;
        for (int i = tid; i < L_; i += 256)
            xsh[nb][i] = xs[side ? (L_ - 1 - i) : i];
    }
    __syncthreads();
    if (tid < 64) {                                 // u init: v = e0
        ulonglong2 z; z.x = 0ull; z.y = 0ull;
        if (tid == 0) {
            float2 xa = xsh[0][0], xb = xsh[1][0];
            asm("mov.b64 %0, {%1,%2};" : "=l"(z.x) : "f"(xa.x), "f"(xa.y));
            asm("mov.b64 %0, {%1,%2};" : "=l"(z.y) : "f"(xb.x), "f"(xb.y));
        }
        *(ulonglong2*)&usm[0][tid][0] = z;
    }
    float v0 = (r == 0) ? 1.0f : 0.0f;
    float v1 = v0;

    const ulonglong2* Wp = (const ulonglong2*)(g_E + (size_t)side * NPAIR * PAIRBLK_U64);
    int tbase = w * 256 + lane;                    // 16B-unit index, chunk stride 32
    ulonglong2 buf[2][8];
    #pragma unroll
    for (int c = 0; c < 8; c++) buf[0][c] = __ldg(Wp + tbase + c * 32);

    for (int P = 0; P < NPAIR; P++) {
        int pb = P & 1;
        if (P < NPAIR - 1) {                       // prefetch next pair (~500 cyc ahead)
            const ulonglong2* nx = Wp + (size_t)(P + 1) * 2048 + tbase;
            #pragma unroll
            for (int c = 0; c < 8; c++) buf[pb ^ 1][c] = __ldg(nx + c * 32);
        }
        #pragma unroll
        for (int e = 0; e < 2; e++) {
            int s = 2 * P + e;
            // W-side cvts: off critical path (before the barrier)
            u64 Ef[16];
            #pragma unroll
            for (int c = 0; c < 8; c++) {
                uint32_t hA = e ? (uint32_t)(buf[pb][c].x >> 32) : (uint32_t)buf[pb][c].x;
                uint32_t hB = e ? (uint32_t)(buf[pb][c].y >> 32) : (uint32_t)buf[pb][c].y;
                float2 fA = __half22float2(*(__half2*)&hA);
                float2 fB = __half22float2(*(__half2*)&hB);
                asm("mov.b64 %0, {%1,%2};" : "=l"(Ef[2 * c])     : "f"(fA.x), "f"(fA.y));
                asm("mov.b64 %0, {%1,%2};" : "=l"(Ef[2 * c + 1]) : "f"(fB.x), "f"(fB.y));
            }
            float2 xc0 = xsh[0][s], xc1 = xsh[1][s];
            float2 xn0 = make_float2(0.f, 0.f), xn1 = xn0;
            if (s < L_ - 1) { xn0 = xsh[0][s + 1]; xn1 = xsh[1][s + 1]; }

            __syncthreads();                        // usm[e] ready (written after prev bar)

            const ulonglong2* ub = (const ulonglong2*)&usm[e][q * 16][0];
            u64 a00 = 0ull, a01 = 0ull, a10 = 0ull, a11 = 0ull;
            #pragma unroll
            for (int j = 0; j < 16; j += 2) {
                ulonglong2 u0 = ub[j];              // l = q*16+j  : (batch0, batch1)
                ulonglong2 u1 = ub[j + 1];
                asm("fma.rn.f32x2 %0, %1, %2, %0;" : "+l"(a00) : "l"(u0.x), "l"(Ef[j]));
                asm("fma.rn.f32x2 %0, %1, %2, %0;" : "+l"(a10) : "l"(u0.y), "l"(Ef[j]));
                asm("fma.rn.f32x2 %0, %1, %2, %0;" : "+l"(a01) : "l"(u1.x), "l"(Ef[j + 1]));
                asm("fma.rn.f32x2 %0, %1, %2, %0;" : "+l"(a11) : "l"(u1.y), "l"(Ef[j + 1]));
            }
            float s0, s1, lo, hi;
            asm("mov.b64 {%0,%1}, %2;" : "=f"(lo), "=f"(hi) : "l"(a00)); s0 = lo + hi;
            asm("mov.b64 {%0,%1}, %2;" : "=f"(lo), "=f"(hi) : "l"(a01)); s0 += lo + hi;
            asm("mov.b64 {%0,%1}, %2;" : "=f"(lo), "=f"(hi) : "l"(a10)); s1 = lo + hi;
            asm("mov.b64 {%0,%1}, %2;" : "=f"(lo), "=f"(hi) : "l"(a11)); s1 += lo + hi;
            s0 += __shfl_xor_sync(0xFFFFFFFFu, s0, 1);
            s1 += __shfl_xor_sync(0xFFFFFFFFu, s1, 1);
            s0 += __shfl_xor_sync(0xFFFFFFFFu, s0, 2);
            s1 += __shfl_xor_sync(0xFFFFFFFFu, s1, 2);
            if (q == 0) {
                float vp0 = s0 + v0 * (xc0.x + xc0.y);
                float vp1 = s1 + v1 * (xc1.x + xc1.y);
                v0 = vp0; v1 = vp1;
                if (s < L_ - 1) {                   // u' for next site, ping-pong buffer
                    ulonglong2 st;
                    asm("mov.b64 %0, {%1,%2};" : "=l"(st.x) : "f"(vp0 * xn0.x), "f"(vp0 * xn0.y));
                    asm("mov.b64 %0, {%1,%2};" : "=l"(st.y) : "f"(vp1 * xn1.x), "f"(vp1 * xn1.y));
                    *(ulonglong2*)&usm[e ^ 1][r][0] = st;
                }
            }
        }
    }
    if (q == 0) {
        if (side) { g_wR[b0][r] = v0; g_wR[b0 + 1][r] = v1; }
        else      { g_vL[b0][r] = v0; g_vL[b0 + 1][r] = v1; }
    }
}

// ---------- output: out[b][o] = sum_l vL[l] * sum_r core[o][l][r] * wR[r] ----------
__global__ void __launch_bounds__(640, 1)
output_kernel(const float* __restrict__ core, float* __restrict__ out) {
    int b = blockIdx.x;
    int tid = threadIdx.x;              // 640 = 10 o * 64 l
    int o = tid >> 6, l = tid & 63;
    __shared__ float wsh[D_];
    __shared__ float red[O_][2];
    if (tid < 64) wsh[tid] = g_wR[b][tid];
    __syncthreads();
    const float4* c4 = (const float4*)(core + (o * D_ + l) * D_);
    const float4* w4 = (const float4*)wsh;
    float s = 0.f;
    #pragma unroll
    for (int k = 0; k < 16; k++) {
        float4 cv = c4[k], wv = w4[k];
        s += cv.x * wv.x + cv.y * wv.y + cv.z * wv.z + cv.w * wv.w;
    }
    s *= g_vL[b][l];
    #pragma unroll
    for (int off = 16; off; off >>= 1) s += __shfl_xor_sync(0xFFFFFFFFu, s, off);
    if ((tid & 31) == 0) red[o][(tid >> 5) & 1] = s;
    __syncthreads();
    if (tid < O_) out[b * O_ + tid] = red[tid][0] + red[tid][1];
}

extern "C" void kernel_launch(void* const* d_in, const int* in_sizes, int n_in,
                              void* d_out, int out_size) {
    const float* x    = (const float*)d_in[0];   // [64, 1024, 2]
    const float* Wl   = (const float*)d_in[1];   // [512, 64, 64, 2]
    const float* core = (const float*)d_in[2];   // [10, 64, 64]
    const float* Wr   = (const float*)d_in[3];   // [512, 64, 64, 2]
    float* out = (float*)d_out;                  // [64, 10]

    cudaFuncSetAttribute(prep_kernel,
                         cudaFuncAttributeMaxDynamicSharedMemorySize, 131072);
    prep_kernel<<<512, 256, 131072>>>(Wl, Wr);
    chain_kernel<<<64, 256>>>(x);
    output_kernel<<<B_, 640>>>(core, out);
}

// round 7
// speedup vs baseline: 3.0417x; 3.0417x over previous
#include <cuda_runtime.h>
#include <cuda_fp16.h>
#include <cstdint>

#define D_ 64
#define B_ 64
#define S_ 1024
#define L_ 512
#define O_ 10

typedef unsigned long long u64;

__device__ float g_vL[B_][D_];
__device__ float g_wR[B_][D_];
// fp16 E = W - I, scan-ordered, side-uniform, thread-major 64B chunks:
// g_E[(side*512+s)*4096 + tid*16 + j] = half2 E_scan[in = (tid&31&3)*16+j][out]
__device__ __align__(16) uint32_t g_E[2 * L_ * 4096];

// ---------- prep ----------
// 1024 blocks: side = bx>>9, scan site s = bx&511. Right side transposed + reversed.
__global__ void __launch_bounds__(256, 4) prep_kernel(
        const float* __restrict__ Wl, const float* __restrict__ Wr) {
    __shared__ float2 tile[D_ * (D_ + 1)];   // tile[in*65 + out] = E_scan source
    int bx = blockIdx.x;
    int side = bx >> 9;
    int s = bx & 511;
    int tid = threadIdx.x;
    if (side == 0) {
        const float2* src = (const float2*)Wl + (size_t)s * 4096;
        for (int i = tid; i < 4096; i += 256) {
            int l = i >> 6, r = i & 63;
            tile[l * 65 + r] = src[i];       // in=l, out=r
        }
    } else {
        const float2* src = (const float2*)Wr + (size_t)(511 - s) * 4096;
        for (int i = tid; i < 4096; i += 256) {
            int l = i >> 6, r = i & 63;
            tile[r * 65 + l] = src[i];       // in=r, out=l (transpose)
        }
    }
    __syncthreads();
    int lane = tid & 31, w = tid >> 5;
    int out = w * 8 + (lane >> 2);
    int q = lane & 3;
    uint32_t* dst = g_E + (size_t)bx * 4096 + tid * 16;
    #pragma unroll
    for (int j = 0; j < 16; j++) {
        int in = q * 16 + j;
        float d = (in == out) ? 1.0f : 0.0f;
        float2 wv = tile[in * 65 + out];
        __half2 h = __floats2half2_rn(wv.x - d, wv.y - d);
        dst[j] = *(uint32_t*)&h;
    }
}

// ---------- chain ----------
// grid 128: side = bx>>6, b = bx&63. 256 threads; warp w owns out = w*8..w*8+7,
// lane = rloc*4 + q; thread handles in = q*16..+16. One __syncthreads per site.
// v'[out] = v[out]*(x0+x1) + sum_in (v[in]x0)*E0[in,out] + (v[in]x1)*E1[in,out]

// per-thread partial over its 16 'in' values; all register indices compile-time
__device__ __forceinline__ float site_partial(
        uint4 a0, uint4 a1, uint4 a2, uint4 a3, const u64* ubase) {
    uint32_t hw[16] = { a0.x, a0.y, a0.z, a0.w, a1.x, a1.y, a1.z, a1.w,
                        a2.x, a2.y, a2.z, a2.w, a3.x, a3.y, a3.z, a3.w };
    const ulonglong2* ub = (const ulonglong2*)ubase;
    u64 acc0 = 0ull, acc1 = 0ull;
    #pragma unroll
    for (int jj = 0; jj < 8; jj++) {
        ulonglong2 uu = ub[jj];              // u for in = 2jj, 2jj+1
        float2 f0 = __half22float2(*(__half2*)&hw[2 * jj]);
        float2 f1 = __half22float2(*(__half2*)&hw[2 * jj + 1]);
        u64 e0, e1;
        asm("mov.b64 %0, {%1,%2};" : "=l"(e0) : "f"(f0.x), "f"(f0.y));
        asm("mov.b64 %0, {%1,%2};" : "=l"(e1) : "f"(f1.x), "f"(f1.y));
        asm("fma.rn.f32x2 %0, %1, %2, %0;" : "+l"(acc0) : "l"(uu.x), "l"(e0));
        asm("fma.rn.f32x2 %0, %1, %2, %0;" : "+l"(acc1) : "l"(uu.y), "l"(e1));
    }
    float l0, h0, l1, h1;
    asm("mov.b64 {%0,%1}, %2;" : "=f"(l0), "=f"(h0) : "l"(acc0));
    asm("mov.b64 {%0,%1}, %2;" : "=f"(l1), "=f"(h1) : "l"(acc1));
    return (l0 + h0) + (l1 + h1);
}

__global__ void __launch_bounds__(256, 1)
chain_kernel(const float* __restrict__ x) {
    __shared__ float2 xsh[L_];
    __shared__ __align__(16) u64 usm[2][72];   // l -> (l>>4)*18 + (l&15)

    int tid = threadIdx.x;
    int lane = tid & 31, w = tid >> 5;
    int q = lane & 3;
    int out = w * 8 + (lane >> 2);
    int side = blockIdx.x >> 6;
    int b = blockIdx.x & 63;
    bool owner = (q == 0);

    const float2* xsrc = (const float2*)x + (size_t)b * S_ + side * L_;
    for (int i = tid; i < L_; i += 256)
        xsh[i] = xsrc[side ? (L_ - 1 - i) : i];
    __syncthreads();
    if (tid < 64) {
        u64 z = 0ull;
        if (tid == 0) {
            float2 x0 = xsh[0];
            asm("mov.b64 %0, {%1,%2};" : "=l"(z) : "f"(x0.x), "f"(x0.y));
        }
        usm[0][(tid >> 4) * 18 + (tid & 15)] = z;
    }
    float v = (out == 0) ? 1.0f : 0.0f;
    const u64* ub0 = &usm[0][q * 18];
    const u64* ub1 = &usm[1][q * 18];
    int ridx = (out >> 4) * 18 + (out & 15);

    const uint4* Ep = (const uint4*)g_E + ((size_t)side << 19) + tid * 4;
    uint4 A0, A1, A2, A3, B0, B1, B2, B3;
    {
        const uint4* p = Ep;
        A0 = __ldg(p); A1 = __ldg(p + 1); A2 = __ldg(p + 2); A3 = __ldg(p + 3);
        p += 1024;
        B0 = __ldg(p); B1 = __ldg(p + 1); B2 = __ldg(p + 2); B3 = __ldg(p + 3);
    }

    for (int s = 0; s < L_; s += 2) {
        // ---- even site s (buffer A, u in usm[0]) ----
        {
            float2 xc = xsh[s];
            float2 xn = xsh[s + 1];
            __syncthreads();
            float ps = site_partial(A0, A1, A2, A3, ub0);
            if (s + 2 < L_) {                        // reload A <- site s+2
                const uint4* p = Ep + (size_t)(s + 2) * 1024;
                A0 = __ldg(p); A1 = __ldg(p + 1); A2 = __ldg(p + 2); A3 = __ldg(p + 3);
            }
            ps += __shfl_xor_sync(0xFFFFFFFFu, ps, 1);
            ps += __shfl_xor_sync(0xFFFFFFFFu, ps, 2);
            if (owner) {
                float vp = ps + v * (xc.x + xc.y);
                v = vp;
                u64 st;
                asm("mov.b64 %0, {%1,%2};" : "=l"(st) : "f"(vp * xn.x), "f"(vp * xn.y));
                usm[1][ridx] = st;
            }
        }
        // ---- odd site s+1 (buffer B, u in usm[1]) ----
        {
            float2 xc = xsh[s + 1];
            float2 xn = (s + 2 < L_) ? xsh[s + 2] : xc;
            __syncthreads();
            float ps = site_partial(B0, B1, B2, B3, ub1);
            if (s + 3 < L_) {                        // reload B <- site s+3
                const uint4* p = Ep + (size_t)(s + 3) * 1024;
                B0 = __ldg(p); B1 = __ldg(p + 1); B2 = __ldg(p + 2); B3 = __ldg(p + 3);
            }
            ps += __shfl_xor_sync(0xFFFFFFFFu, ps, 1);
            ps += __shfl_xor_sync(0xFFFFFFFFu, ps, 2);
            if (owner) {
                float vp = ps + v * (xc.x + xc.y);
                v = vp;
                if (s + 2 < L_) {
                    u64 st;
                    asm("mov.b64 %0, {%1,%2};" : "=l"(st) : "f"(vp * xn.x), "f"(vp * xn.y));
                    usm[0][ridx] = st;
                }
            }
        }
    }
    if (owner) {
        if (side) g_wR[b][out] = v;
        else      g_vL[b][out] = v;
    }
}

// ---------- output: out[b][o] = sum_l vL[l] * sum_r core[o][l][r] * wR[r] ----------
__global__ void __launch_bounds__(640, 1)
output_kernel(const float* __restrict__ core, float* __restrict__ out) {
    int b = blockIdx.x;
    int tid = threadIdx.x;              // 640 = 10 o * 64 l
    int o = tid >> 6, l = tid & 63;
    __shared__ float wsh[D_];
    __shared__ float red[O_][2];
    if (tid < 64) wsh[tid] = g_wR[b][tid];
    __syncthreads();
    const float4* c4 = (const float4*)(core + (o * D_ + l) * D_);
    const float4* w4 = (const float4*)wsh;
    float s = 0.f;
    #pragma unroll
    for (int k = 0; k < 16; k++) {
        float4 cv = c4[k], wv = w4[k];
        s += cv.x * wv.x + cv.y * wv.y + cv.z * wv.z + cv.w * wv.w;
    }
    s *= g_vL[b][l];
    #pragma unroll
    for (int off = 16; off; off >>= 1) s += __shfl_xor_sync(0xFFFFFFFFu, s, off);
    if ((tid & 31) == 0) red[o][(tid >> 5) & 1] = s;
    __syncthreads();
    if (tid < O_) out[b * O_ + tid] = red[tid][0] + red[tid][1];
}

extern "C" void kernel_launch(void* const* d_in, const int* in_sizes, int n_in,
                              void* d_out, int out_size) {
    const float* x    = (const float*)d_in[0];   // [64, 1024, 2]
    const float* Wl   = (const float*)d_in[1];   // [512, 64, 64, 2]
    const float* core = (const float*)d_in[2];   // [10, 64, 64]
    const float* Wr   = (const float*)d_in[3];   // [512, 64, 64, 2]
    float* out = (float*)d_out;                  // [64, 10]

    prep_kernel<<<2 * L_, 256>>>(Wl, Wr);
    chain_kernel<<<128, 256>>>(x);
    output_kernel<<<B_, 640>>>(core, out);
}